// round 17
// baseline (speedup 1.0000x reference)
#include <cuda_runtime.h>

#define NB 32
#define NC 3
#define NH 256
#define NW 256
#define KS 29
#define PADK 14
#define HID 32
#define TY 16
#define TX 16
#define HW (NH*NW)
#define NPIX (NB*NC*NH*NW)
#define NBLK (NB*(NH/TY)*(NW/TX))   // 8192
#define CTHREADS 288                // 9 warps: one per hidden row-pair

typedef unsigned long long u64t;

__device__ float g_z2[NB*NC*HW];
__device__ float g_partials[NBLK];
__device__ int   g_done = 0;

// ---------------- packed f32x2 helpers (sm_103a) ----------------
__device__ __forceinline__ u64t pk2(float a, float b) {
    u64t r; asm("mov.b64 %0, {%1,%2};" : "=l"(r) : "f"(a), "f"(b)); return r;
}
__device__ __forceinline__ void upk2(u64t v, float& a, float& b) {
    asm("mov.b64 {%0,%1}, %2;" : "=f"(a), "=f"(b) : "l"(v));
}
__device__ __forceinline__ u64t fma2(u64t a, u64t b, u64t c) {
    u64t d; asm("fma.rn.f32x2 %0, %1, %2, %3;" : "=l"(d) : "l"(a), "l"(b), "l"(c));
    return d;
}
__device__ __forceinline__ void lds2u64(unsigned s, u64t& a, u64t& b) {
    asm volatile("ld.shared.v2.u64 {%0,%1}, [%2];" : "=l"(a), "=l"(b) : "r"(s));
}

// ---------------------------------------------------------------------------
// 1) fused separable blur (reflect), f32x2 packed, taps computed in-block.
//    (unchanged from last passing measurement)
// ---------------------------------------------------------------------------
#define BXIN 0
#define BVT  15360
#define BKK  23584
#define BLUR_SMEM ((23584 + 32) * 4)

__global__ __launch_bounds__(256, 2)
void blur_kernel(const float* __restrict__ x,
                 const int* __restrict__ t,
                 const float* __restrict__ sched) {
    extern __shared__ float s[];
    float* xin  = s + BXIN;
    float* vt   = s + BVT;
    float* kk   = s + BKK;
    float* hout = s + BXIN;

    int bc = blockIdx.y;
    int b  = bc / NC;
    int y0 = blockIdx.x * 32;
    int tid = threadIdx.x;

    if (tid < 32) {
        float sigma = sched[t[b]];
        float val = 0.f;
        if (tid < KS) {
            float xg = (float)(tid - PADK) / sigma;
            val = expf(-0.5f * xg * xg);
        }
        float ssum = val;
#pragma unroll
        for (int off = 16; off; off >>= 1)
            ssum += __shfl_xor_sync(0xffffffffu, ssum, off);
        if (tid < KS) kk[tid] = val / ssum;
    }

    const float* src = x + (size_t)bc * HW;
    int c4 = (tid & 63) * 4;
    for (int i = tid >> 6; i < 60; i += 4) {
        int gy = y0 - PADK + i;
        gy = gy < 0 ? -gy : (gy > NH-1 ? 2*(NH-1) - gy : gy);
        *(float4*)&xin[i*256 + c4] = *(const float4*)&src[gy*NW + c4];
    }
    __syncthreads();

    {
        u64t kv[KS];
#pragma unroll
        for (int k = 0; k < KS; k++) kv[k] = pk2(kk[k], kk[k]);
        int cp = tid & 127, half = tid >> 7;
#pragma unroll 1
        for (int c2 = 0; c2 < 2; c2++) {
            int cr = (half*2 + c2) * 8;
            u64t acc[8] = {0,0,0,0,0,0,0,0};
#pragma unroll
            for (int i = 0; i < 36; i++) {
                u64t v = *(const u64t*)&xin[(cr + i)*256 + 2*cp];
#pragma unroll
                for (int a = 0; a < 8; a++) {
                    int k = i - a;
                    if (k >= 0 && k < KS) acc[a] = fma2(kv[k], v, acc[a]);
                }
            }
#pragma unroll
            for (int a = 0; a < 8; a++) {
                float lo, hi; upk2(acc[a], lo, hi);
                vt[(cr + a)*257 + 2*cp]     = lo;
                vt[(cr + a)*257 + 2*cp + 1] = hi;
            }
        }
    }
    __syncthreads();

    {
        u64t kh[KS+1];
        kh[0]  = pk2(kk[0], 0.f);
#pragma unroll
        for (int m = 1; m < KS; m++) kh[m] = pk2(kk[m], kk[m-1]);
        kh[KS] = pk2(0.f, kk[KS-1]);
#pragma unroll 1
        for (int it = 0; it < 2; it++) {
            int task = tid + it*256;
            int rr = task & 31, cs = (task >> 5) * 16;
            u64t acc[8] = {0,0,0,0,0,0,0,0};
#pragma unroll
            for (int i = 0; i < 44; i++) {
                int col = cs - PADK + i;
                col = col < 0 ? -col : (col > NW-1 ? 2*(NW-1) - col : col);
                float v = vt[rr*257 + col];
                u64t vv = pk2(v, v);
#pragma unroll
                for (int a = 0; a < 8; a++) {
                    int m = i - 2*a;
                    if (m >= 0 && m <= KS) acc[a] = fma2(kh[m], vv, acc[a]);
                }
            }
#pragma unroll
            for (int a = 0; a < 8; a++) {
                float lo, hi; upk2(acc[a], lo, hi);
                hout[rr*257 + cs + 2*a]     = lo;
                hout[rr*257 + cs + 2*a + 1] = hi;
            }
        }
    }
    __syncthreads();

    float* dst = g_z2 + (size_t)bc * HW + (size_t)y0 * NW;
#pragma unroll 1
    for (int r2 = 0; r2 < 32; r2++)
        dst[r2*NW + tid] = hout[r2*257 + tid];
}

// ---------------------------------------------------------------------------
// 2) fused conv1+relu+conv2+loss+final reduce.  288 threads (9 warps).
//    conv1: lane = output channel, weights in REGISTERS, warp = row-pair
//    (all 9 pairs static, no runtime-bound loops).
//    smem floats: hs[11664] @0 | zs[1200] @11664 | ws2[864] @12864 | misc[48]
// ---------------------------------------------------------------------------
#define CHS   0
#define CZS   11664
#define CWS2  12864
#define CMISC 13728
#define CONV_SMEM (13824 * 4)

// Hidden row-pair pr (rows 2pr, 2pr+1), output cols 0..17 (all static).
// Lane owns channel o; weights wr[27] in registers; z broadcast from smem.
__device__ __forceinline__ void conv1_pair(
    const float* __restrict__ zs, float* __restrict__ hs,
    const float* wr, float base, int o,
    int pr, int x0, int y0)
{
    int hr0 = 2*pr;
    int gy0 = y0 - 1 + hr0;
    bool rok0 = (unsigned)gy0 < NH;
    bool rok1 = (unsigned)(gy0+1) < NH;
    float A0=0.f,A1=0.f,B0=0.f,B1=0.f,C0=0.f,C1=0.f;
#pragma unroll
    for (int g = 0; g < 10; g++) {
        float2 zf[3][4];
#pragma unroll
        for (int ch = 0; ch < 3; ch++)
#pragma unroll
            for (int r4 = 0; r4 < 4; r4++)
                zf[ch][r4] = *(const float2*)&zs[ch*400 + (hr0 + r4)*20 + 2*g];
#pragma unroll
        for (int half = 0; half < 2; half++) {
            int ic = 2*g + half;                 // compile-time constant
            bool doC = ic < 18;
            bool doB = (ic >= 1) && (ic <= 18);
            bool doA = ic >= 2;
            if (doC) { C0 = base; C1 = base; }
#pragma unroll
            for (int ch = 0; ch < 3; ch++)
#pragma unroll
                for (int r4 = 0; r4 < 4; r4++) {
                    float zv = half ? zf[ch][r4].y : zf[ch][r4].x;
                    if (r4 <= 2) {
                        if (doA) A0 = fmaf(wr[ch*9 + r4*3 + 2], zv, A0);
                        if (doB) B0 = fmaf(wr[ch*9 + r4*3 + 1], zv, B0);
                        if (doC) C0 = fmaf(wr[ch*9 + r4*3 + 0], zv, C0);
                    }
                    if (r4 >= 1) {
                        if (doA) A1 = fmaf(wr[ch*9 + (r4-1)*3 + 2], zv, A1);
                        if (doB) B1 = fmaf(wr[ch*9 + (r4-1)*3 + 1], zv, B1);
                        if (doC) C1 = fmaf(wr[ch*9 + (r4-1)*3 + 0], zv, C1);
                    }
                }
            if (doA) {
                int oc = ic - 2;
                int gx = x0 - 1 + oc;
                bool cok = (unsigned)gx < NW;
                float h0 = (rok0 && cok) ? fmaxf(A0, 0.f) : 0.f;
                float h1 = (rok1 && cok) ? fmaxf(A1, 0.f) : 0.f;
                hs[(hr0*18 + oc)*36 + o]     = h0;
                hs[((hr0+1)*18 + oc)*36 + o] = h1;
            }
            A0 = B0; A1 = B1; B0 = C0; B1 = C1;
        }
    }
}

__global__ __launch_bounds__(CTHREADS, 3)
void conv_loss_kernel(const float* __restrict__ x,
                      const int* __restrict__ t,
                      const float* __restrict__ W1,
                      const float* __restrict__ b1,
                      const float* __restrict__ tw,
                      const float* __restrict__ W2,
                      const float* __restrict__ b2,
                      float* __restrict__ out) {
    extern __shared__ float sm[];
    float* hs   = sm + CHS;
    float* zs   = sm + CZS;
    float* ws2  = sm + CWS2;
    float* misc = sm + CMISC;

    unsigned smem_u = (unsigned)__cvta_generic_to_shared(sm);
    int tid = threadIdx.x;
    int bx = blockIdx.x, by = blockIdx.y, b = blockIdx.z;
    int x0 = bx*TX, y0 = by*TY;

    // conv2 weights -> smem (tap-major x32)
    for (int i = tid; i < NC*HID*9; i += CTHREADS) {
        int co = i / 288, rem = i % 288, o2 = rem / 9, tap = rem % 9;
        ws2[(co*9 + tap)*32 + o2] = W2[i];
    }
    float tn = (float)t[b] * (1.0f / 1000.0f);

    // z tile with halo 2
    const float* zsrc = g_z2 + (size_t)b*NC*HW;
    for (int i = tid; i < NC*20*20; i += CTHREADS) {
        int ch = i / 400, rr = (i / 20) % 20, cc = i % 20;
        int gy = y0 - 2 + rr, gx = x0 - 2 + cc;
        float v = 0.f;
        if ((unsigned)gy < NH && (unsigned)gx < NW)
            v = zsrc[ch*HW + gy*NW + gx];
        zs[i] = v;
    }
    __syncthreads();

    // --- conv1: lane = channel o, warp w in 0..8 handles row-pair w ---
    {
        int wid = tid >> 5, o = tid & 31;
        float wr[27];
#pragma unroll
        for (int j = 0; j < 27; j++) wr[j] = __ldg(&W1[o*27 + j]);
        float base = fmaf(tn, __ldg(&tw[o]), __ldg(&b1[o]));
        conv1_pair(zs, hs, wr, base, o, wid, x0, y0);
    }
    __syncthreads();

    // --- conv2: 64 threads, 2x2 pixels each; f32x2 over channel pairs ---
    float e = 0.f;
    if (tid < 64) {
        int c = (tid & 7) * 2, r = (tid >> 3) * 2;
        u64t acc[2][2][3];
#pragma unroll
        for (int i = 0; i < 2; i++)
#pragma unroll
            for (int j = 0; j < 2; j++)
#pragma unroll
                for (int co = 0; co < 3; co++) acc[i][j][co] = 0ULL;

        unsigned wbase = smem_u + CWS2*4;
        unsigned hb = smem_u + (unsigned)((r*18 + c)*36)*4;
#pragma unroll 1
        for (int og = 0; og < 8; og++) {
            u64t hc[2][4][2];
#pragma unroll
            for (int u = 0; u < 4; u++) {
                lds2u64(hb + (unsigned)((u*18 + 0)*36)*4 + og*16, hc[0][u][0], hc[0][u][1]);
                lds2u64(hb + (unsigned)((u*18 + 1)*36)*4 + og*16, hc[1][u][0], hc[1][u][1]);
            }
#pragma unroll
            for (int kx = 0; kx < 3; kx++) {
                u64t (*h0)[2] = hc[kx & 1];
                u64t (*h1)[2] = hc[(kx + 1) & 1];
#pragma unroll
                for (int co = 0; co < 3; co++)
#pragma unroll
                    for (int ky = 0; ky < 3; ky++) {
                        u64t wx, wy;
                        lds2u64(wbase + (unsigned)((co*9 + ky*3 + kx)*8 + og)*16, wx, wy);
                        acc[0][0][co] = fma2(wx, h0[ky][0],   acc[0][0][co]);
                        acc[0][0][co] = fma2(wy, h0[ky][1],   acc[0][0][co]);
                        acc[0][1][co] = fma2(wx, h1[ky][0],   acc[0][1][co]);
                        acc[0][1][co] = fma2(wy, h1[ky][1],   acc[0][1][co]);
                        acc[1][0][co] = fma2(wx, h0[ky+1][0], acc[1][0][co]);
                        acc[1][0][co] = fma2(wy, h0[ky+1][1], acc[1][0][co]);
                        acc[1][1][co] = fma2(wx, h1[ky+1][0], acc[1][1][co]);
                        acc[1][1][co] = fma2(wy, h1[ky+1][1], acc[1][1][co]);
                    }
                if (kx < 2) {
#pragma unroll
                    for (int u = 0; u < 4; u++)
                        lds2u64(hb + (unsigned)((u*18 + (kx+2))*36)*4 + og*16,
                                hc[kx & 1][u][0], hc[kx & 1][u][1]);
                }
            }
        }
        int gy = y0 + r, gx = x0 + c;
        const float* xb = x + (size_t)b*NC*HW + gy*NW + gx;
#pragma unroll
        for (int co = 0; co < 3; co++) {
            float bco = __ldg(&b2[co]);
#pragma unroll
            for (int i = 0; i < 2; i++)
#pragma unroll
                for (int j = 0; j < 2; j++) {
                    float lo, hi; upk2(acc[i][j][co], lo, hi);
                    float pr = lo + hi + bco;
                    float d = xb[co*HW + i*NW + j] - pr;
                    e += d*d;
                }
        }
    }

    // block reduce (9 warps)
#pragma unroll
    for (int off = 16; off; off >>= 1) e += __shfl_down_sync(0xffffffffu, e, off);
    float* wsum = misc;
    if ((tid & 31) == 0) wsum[tid >> 5] = e;
    __syncthreads();
    __shared__ int s_last;
    if (tid == 0) {
        float v = 0.f;
#pragma unroll
        for (int w = 0; w < 9; w++) v += wsum[w];
        g_partials[(b*16 + by)*16 + bx] = v;
        __threadfence();
        int old = atomicAdd(&g_done, 1);
        s_last = (old == NBLK - 1);
    }
    __syncthreads();

    if (s_last) {
        double acc = 0.0;
        for (int i = tid; i < NBLK; i += CTHREADS) acc += (double)g_partials[i];
#pragma unroll
        for (int off = 16; off; off >>= 1)
            acc += __shfl_down_sync(0xffffffffu, acc, off);
        double* sh2 = (double*)sm;
        if ((tid & 31) == 0) sh2[tid >> 5] = acc;
        __syncthreads();
        if (tid == 0) {
            double v = 0.0;
#pragma unroll
            for (int w = 0; w < 9; w++) v += sh2[w];
            out[0] = (float)(v / (double)NPIX);
            g_done = 0;
        }
    }
}

// ---------------------------------------------------------------------------
extern "C" void kernel_launch(void* const* d_in, const int* in_sizes, int n_in,
                              void* d_out, int out_size) {
    const float* x     = (const float*)d_in[0];
    const int*   t     = (const int*)  d_in[1];
    const float* W1    = (const float*)d_in[2];
    const float* b1    = (const float*)d_in[3];
    const float* tw    = (const float*)d_in[4];
    const float* W2    = (const float*)d_in[5];
    const float* b2    = (const float*)d_in[6];
    const float* sched = (const float*)d_in[7];

    cudaFuncSetAttribute(blur_kernel,
                         cudaFuncAttributeMaxDynamicSharedMemorySize, BLUR_SMEM);
    blur_kernel<<<dim3(NH/32, NB*NC), 256, BLUR_SMEM>>>(x, t, sched);

    cudaFuncSetAttribute(conv_loss_kernel,
                         cudaFuncAttributeMaxDynamicSharedMemorySize, CONV_SMEM);
    conv_loss_kernel<<<dim3(NW/TX, NH/TY, NB), CTHREADS, CONV_SMEM>>>(
        x, t, W1, b1, tw, W2, b2, (float*)d_out);
}